// round 5
// baseline (speedup 1.0000x reference)
#include <cuda_runtime.h>
#include <cuda_fp16.h>
#include <cstdint>
#include <cstddef>

#define G   256
#define CH  128
#define HD  64
#define NTHREADS 512

// ---- smem byte offsets (tiles: [row][64 halves] = 128B rows, SW128 swizzle) ----
#define SB_OFF  0                        // bias: 192 floats
#define XT_OFF  1024                     // 2 x [256][64] fp16 (ch-chunks) = 64 KB
#define WT_OFF  (XT_OFF + 2*32768)       // 2 x [192][64] fp16 (ch-chunks) = 48 KB
#define Q_OFF   (WT_OFF + 2*24576)       // [256][64] fp16 (pre-scaled)    = 32 KB
#define K_OFF   (Q_OFF  + 32768)         // [256][64] fp16                 = 32 KB
#define V_OFF   (K_OFF  + 32768)         // [256][64] fp16                 = 32 KB
#define SMEM_BYTES (V_OFF + 32768)       // 214016

#define SWZ(o) ((o) ^ (((o) >> 3) & 0x70))
#define ESC2 0.12751743f                 // (1/sqrt(128)) * log2(e)

__device__ __forceinline__ uint32_t smem_u32(const void* p) {
    uint32_t a;
    asm("{ .reg .u64 t; cvta.to.shared.u64 t, %1; cvt.u32.u64 %0, t; }" : "=r"(a) : "l"(p));
    return a;
}
__device__ __forceinline__ uint32_t h2u(float a, float b) {
    __half2 h = __floats2half2_rn(a, b);
    return *reinterpret_cast<uint32_t*>(&h);
}
__device__ __forceinline__ float ex2f(float x) {
    float r; asm("ex2.approx.f32 %0, %1;" : "=f"(r) : "f"(x)); return r;
}
__device__ __forceinline__ void ldsm4(uint32_t* r, uint32_t addr) {
    asm volatile("ldmatrix.sync.aligned.m8n8.x4.shared.b16 {%0,%1,%2,%3}, [%4];"
                 : "=r"(r[0]), "=r"(r[1]), "=r"(r[2]), "=r"(r[3]) : "r"(addr));
}
__device__ __forceinline__ void ldsm4t(uint32_t* r, uint32_t addr) {
    asm volatile("ldmatrix.sync.aligned.m8n8.x4.trans.shared.b16 {%0,%1,%2,%3}, [%4];"
                 : "=r"(r[0]), "=r"(r[1]), "=r"(r[2]), "=r"(r[3]) : "r"(addr));
}
__device__ __forceinline__ void mma16816(float* d, const uint32_t* a, uint32_t b0, uint32_t b1) {
    asm volatile("mma.sync.aligned.m16n8k16.row.col.f32.f16.f16.f32 "
        "{%0,%1,%2,%3}, {%4,%5,%6,%7}, {%8,%9}, {%0,%1,%2,%3};"
        : "+f"(d[0]), "+f"(d[1]), "+f"(d[2]), "+f"(d[3])
        : "r"(a[0]), "r"(a[1]), "r"(a[2]), "r"(a[3]), "r"(b0), "r"(b1));
}

__global__ void __launch_bounds__(NTHREADS, 1)
msa_hmma3(const float* __restrict__ x, const float* __restrict__ W,
          const float* __restrict__ bias, float* __restrict__ out)
{
    extern __shared__ char smem[];
    const uint32_t sb = smem_u32(smem);
    float* sB = reinterpret_cast<float*>(smem + SB_OFF);

    const int h  = blockIdx.x & 1;
    const int bl = blockIdx.x >> 1;
    const int t  = threadIdx.x;
    const int w  = t >> 5, lane = t & 31;
    const int q2 = 2 * (lane & 3);

    // ================= staging: X (256 tokens) + W slice + bias =================
    {   // X: thread -> (token = t>>1, ch-half = t&1)
        const int tok = t >> 1, which = t & 1;
        const float4* xg = reinterpret_cast<const float4*>(
            x + ((size_t)(bl * G + tok)) * CH + which * 64);
        char* p = smem + XT_OFF + which * 32768;
        #pragma unroll
        for (int i = 0; i < 16; i++) {
            float4 v = xg[i];
            *reinterpret_cast<uint2*>(p + SWZ(tok * 128 + i * 8)) =
                make_uint2(h2u(v.x, v.y), h2u(v.z, v.w));
        }
    }
    if (t < 384) {   // W slice
        const int r = t >> 1, which = t & 1;
        const int grow = (r >> 6) * CH + h * HD + (r & 63);
        const float4* wg = reinterpret_cast<const float4*>(W + (size_t)grow * CH + which * 64);
        char* p = smem + WT_OFF + which * 24576;
        #pragma unroll
        for (int i = 0; i < 16; i++) {
            float4 v = wg[i];
            *reinterpret_cast<uint2*>(p + SWZ(r * 128 + i * 8)) =
                make_uint2(h2u(v.x, v.y), h2u(v.z, v.w));
        }
    }
    if (t < 192) sB[t] = bias[(t >> 6) * CH + h * HD + (t & 63)];
    __syncthreads();

    // ================= phase 1: QKV GEMM, warp = 32 rows x 96 cols =================
    {
        const int mt = w >> 1, nh = w & 1;

        // A fragments: 32 rows x 128 ch  (16 ldsm4 = 64 regs, persistent)
        uint32_t xa[16][4];
        #pragma unroll
        for (int m = 0; m < 2; m++)
            #pragma unroll
            for (int ks = 0; ks < 8; ks++) {
                const int r = 32 * mt + 16 * m + (lane & 15);
                const int c = (ks & 3) * 16 + ((lane & 16) ? 8 : 0);
                ldsm4(xa[m * 8 + ks], sb + XT_OFF + (ks >> 2) * 32768 + SWZ(r * 128 + c * 2));
            }

        const int row0 = 32 * mt + (lane >> 2);

        #pragma unroll 1
        for (int chk = 0; chk < 3; chk++) {
            const int g0 = nh * 96 + chk * 32;          // global output col base
            float fa[2][4][4];
            #pragma unroll
            for (int m = 0; m < 2; m++)
                #pragma unroll
                for (int jj = 0; jj < 4; jj++) {
                    fa[m][jj][0]=0.f; fa[m][jj][1]=0.f; fa[m][jj][2]=0.f; fa[m][jj][3]=0.f;
                }

            #pragma unroll
            for (int ks = 0; ks < 8; ks++)
                #pragma unroll
                for (int j = 0; j < 2; j++) {
                    const int n = g0 + 16 * j + (lane & 7) + ((lane & 16) ? 8 : 0);
                    const int c = (ks & 3) * 16 + ((lane & 8) ? 8 : 0);
                    uint32_t b[4];
                    ldsm4(b, sb + WT_OFF + (ks >> 2) * 24576 + SWZ(n * 128 + c * 2));
                    mma16816(fa[0][2*j],   xa[ks],     b[0], b[1]);
                    mma16816(fa[0][2*j+1], xa[ks],     b[2], b[3]);
                    mma16816(fa[1][2*j],   xa[8 + ks], b[0], b[1]);
                    mma16816(fa[1][2*j+1], xa[8 + ks], b[2], b[3]);
                }

            // epilogue: route chunk (fully inside Q, K or V) with bias (+scale for Q)
            char* dst; int col0; bool isq = false;
            if (g0 < 64)        { dst = smem + Q_OFF; col0 = g0;       isq = true; }
            else if (g0 < 128)  { dst = smem + K_OFF; col0 = g0 - 64; }
            else                { dst = smem + V_OFF; col0 = g0 - 128; }

            #pragma unroll
            for (int m = 0; m < 2; m++) {
                const int r0 = row0 + 16 * m;
                #pragma unroll
                for (int jj = 0; jj < 4; jj++) {
                    const int cc = col0 + 8 * jj + q2;
                    const float b0 = sB[g0 + 8 * jj + q2], b1 = sB[g0 + 8 * jj + q2 + 1];
                    float d0 = fa[m][jj][0] + b0, d1 = fa[m][jj][1] + b1;
                    float d2 = fa[m][jj][2] + b0, d3 = fa[m][jj][3] + b1;
                    if (isq) { d0 *= ESC2; d1 *= ESC2; d2 *= ESC2; d3 *= ESC2; }
                    *reinterpret_cast<uint32_t*>(dst + SWZ( r0      * 128 + cc * 2)) = h2u(d0, d1);
                    *reinterpret_cast<uint32_t*>(dst + SWZ((r0 + 8) * 128 + cc * 2)) = h2u(d2, d3);
                }
            }
        }
    }
    __syncthreads();

    // ================= phase 2: attention (warp owns 16 query rows) =================
    uint32_t qa[4][4];
    #pragma unroll
    for (int ks = 0; ks < 4; ks++) {
        const int r = 16 * w + (lane & 15);
        const int c = 16 * ks + ((lane & 16) ? 8 : 0);
        ldsm4(qa[ks], sb + Q_OFF + SWZ(r * 128 + c * 2));
    }

    float oacc[8][4];
    #pragma unroll
    for (int j = 0; j < 8; j++) { oacc[j][0]=0.f; oacc[j][1]=0.f; oacc[j][2]=0.f; oacc[j][3]=0.f; }
    float rsum0 = 0.f, rsum1 = 0.f;

    #pragma unroll 1
    for (int kv = 0; kv < 4; kv++) {
        // S = Q K^T over 64 kv tokens (scale+log2e pre-folded into Q)
        float sacc[8][4];
        #pragma unroll
        for (int j = 0; j < 8; j++) { sacc[j][0]=0.f; sacc[j][1]=0.f; sacc[j][2]=0.f; sacc[j][3]=0.f; }

        #pragma unroll
        for (int ks = 0; ks < 4; ks++)
            #pragma unroll
            for (int j = 0; j < 4; j++) {
                const int n = kv * 64 + 16 * j + (lane & 7) + ((lane & 16) ? 8 : 0);
                const int c = ks * 16 + ((lane & 8) ? 8 : 0);
                uint32_t b[4];
                ldsm4(b, sb + K_OFF + SWZ(n * 128 + c * 2));
                mma16816(sacc[2*j],   qa[ks], b[0], b[1]);
                mma16816(sacc[2*j+1], qa[ks], b[2], b[3]);
            }

        // 2^s (bounded scores, no max-sub) -> P A-fragments
        uint32_t pf[4][4];
        #pragma unroll
        for (int ks = 0; ks < 4; ks++) {
            float e0 = ex2f(sacc[2*ks][0]),   e1 = ex2f(sacc[2*ks][1]);
            float e2 = ex2f(sacc[2*ks][2]),   e3 = ex2f(sacc[2*ks][3]);
            float f0 = ex2f(sacc[2*ks+1][0]), f1 = ex2f(sacc[2*ks+1][1]);
            float f2 = ex2f(sacc[2*ks+1][2]), f3 = ex2f(sacc[2*ks+1][3]);
            rsum0 += (e0 + e1) + (f0 + f1);
            rsum1 += (e2 + e3) + (f2 + f3);
            pf[ks][0] = h2u(e0, e1);
            pf[ks][1] = h2u(e2, e3);
            pf[ks][2] = h2u(f0, f1);
            pf[ks][3] = h2u(f2, f3);
        }

        // O += P V   (B from V[tok][ch] via ldmatrix.trans)
        #pragma unroll
        for (int ks = 0; ks < 4; ks++)
            #pragma unroll
            for (int j = 0; j < 4; j++) {
                const int tok = kv * 64 + ks * 16 + (lane & 7) + ((lane & 8) ? 8 : 0);
                const int ch  = 16 * j + ((lane & 16) ? 8 : 0);
                uint32_t b[4];
                ldsm4t(b, sb + V_OFF + SWZ(tok * 128 + ch * 2));
                mma16816(oacc[2*j],   pf[ks], b[0], b[1]);
                mma16816(oacc[2*j+1], pf[ks], b[2], b[3]);
            }
    }

    // normalize + write out
    rsum0 += __shfl_xor_sync(0xffffffffu, rsum0, 1);
    rsum0 += __shfl_xor_sync(0xffffffffu, rsum0, 2);
    rsum1 += __shfl_xor_sync(0xffffffffu, rsum1, 1);
    rsum1 += __shfl_xor_sync(0xffffffffu, rsum1, 2);
    const float inv0 = 1.0f / rsum0, inv1 = 1.0f / rsum1;

    const int orow = 16 * w + (lane >> 2);
    float* o = out + ((size_t)(bl * G) + orow) * CH + h * HD;
    #pragma unroll
    for (int j = 0; j < 8; j++) {
        const int c = 8 * j + q2;
        *reinterpret_cast<float2*>(o + c) =
            make_float2(oacc[j][0] * inv0, oacc[j][1] * inv0);
        *reinterpret_cast<float2*>(o + 8 * CH + c) =
            make_float2(oacc[j][2] * inv1, oacc[j][3] * inv1);
    }
}

extern "C" void kernel_launch(void* const* d_in, const int* in_sizes, int n_in,
                              void* d_out, int out_size) {
    (void)n_in; (void)out_size;
    const float* x  = (const float*)d_in[0];
    const float* W  = (const float*)d_in[1];
    const float* b  = (const float*)d_in[2];
    float* out = (float*)d_out;

    cudaFuncSetAttribute(msa_hmma3, cudaFuncAttributeMaxDynamicSharedMemorySize, SMEM_BYTES);
    int nbl = in_sizes[0] / (G * CH);   // 512 (b,l) groups
    msa_hmma3<<<nbl * 2, NTHREADS, SMEM_BYTES>>>(x, W, b, out);
}

// round 7
// speedup vs baseline: 1.2480x; 1.2480x over previous
#include <cuda_runtime.h>
#include <cuda_fp16.h>
#include <cstdint>
#include <cstddef>

#define G   256
#define CH  128
#define HD  64
#define NTHREADS 512

// ---- smem byte offsets (tiles: [row][64 halves] = 128B rows, SW128 swizzle) ----
#define SB_OFF  0                        // bias: 192 floats
#define XT_OFF  1024                     // 2 x [256][64] fp16 (ch-chunks) = 64 KB
#define WT_OFF  (XT_OFF + 2*32768)       // 2 x [192][64] fp16 (ch-chunks) = 48 KB
#define K_OFF   (WT_OFF + 2*24576)       // [256][64] fp16                 = 32 KB
#define V_OFF   (K_OFF  + 32768)         // [256][64] fp16                 = 32 KB
#define SMEM_BYTES (V_OFF + 32768)       // 181248

#define SWZ(o) ((o) ^ (((o) >> 3) & 0x70))
#define ESC2 0.12751744f                 // (1/sqrt(128)) * log2(e)

__device__ __forceinline__ uint32_t smem_u32(const void* p) {
    uint32_t a;
    asm("{ .reg .u64 t; cvta.to.shared.u64 t, %1; cvt.u32.u64 %0, t; }" : "=r"(a) : "l"(p));
    return a;
}
__device__ __forceinline__ uint32_t h2u(float a, float b) {
    __half2 h = __floats2half2_rn(a, b);
    return *reinterpret_cast<uint32_t*>(&h);
}
__device__ __forceinline__ float ex2f(float x) {
    float r; asm("ex2.approx.f32 %0, %1;" : "=f"(r) : "f"(x)); return r;
}
__device__ __forceinline__ void ldsm4(uint32_t* r, uint32_t addr) {
    asm volatile("ldmatrix.sync.aligned.m8n8.x4.shared.b16 {%0,%1,%2,%3}, [%4];"
                 : "=r"(r[0]), "=r"(r[1]), "=r"(r[2]), "=r"(r[3]) : "r"(addr));
}
__device__ __forceinline__ void ldsm4t(uint32_t* r, uint32_t addr) {
    asm volatile("ldmatrix.sync.aligned.m8n8.x4.trans.shared.b16 {%0,%1,%2,%3}, [%4];"
                 : "=r"(r[0]), "=r"(r[1]), "=r"(r[2]), "=r"(r[3]) : "r"(addr));
}
__device__ __forceinline__ void mma16816(float* d, const uint32_t* a, uint32_t b0, uint32_t b1) {
    asm volatile("mma.sync.aligned.m16n8k16.row.col.f32.f16.f16.f32 "
        "{%0,%1,%2,%3}, {%4,%5,%6,%7}, {%8,%9}, {%0,%1,%2,%3};"
        : "+f"(d[0]), "+f"(d[1]), "+f"(d[2]), "+f"(d[3])
        : "r"(a[0]), "r"(a[1]), "r"(a[2]), "r"(a[3]), "r"(b0), "r"(b1));
}

__global__ void __launch_bounds__(NTHREADS, 1)
msa_hmma5(const float* __restrict__ x, const float* __restrict__ W,
          const float* __restrict__ bias, float* __restrict__ out)
{
    extern __shared__ char smem[];
    const uint32_t sb = smem_u32(smem);
    float* sB = reinterpret_cast<float*>(smem + SB_OFF);

    const int h  = blockIdx.x & 1;
    const int bl = blockIdx.x >> 1;
    const int t  = threadIdx.x;
    const int w  = t >> 5, lane = t & 31;
    const int q2 = 2 * (lane & 3);

    // ================= staging: X (all 256 tokens) + W slice + bias =================
    {   // X: thread -> (token = t>>1, ch-half = t&1): 16 float4 each
        const int tok = t >> 1, which = t & 1;
        const float4* xg = reinterpret_cast<const float4*>(
            x + ((size_t)(bl * G + tok)) * CH + which * 64);
        char* p = smem + XT_OFF + which * 32768;
        #pragma unroll
        for (int i = 0; i < 16; i++) {
            float4 v = xg[i];
            *reinterpret_cast<uint2*>(p + SWZ(tok * 128 + i * 8)) =
                make_uint2(h2u(v.x, v.y), h2u(v.z, v.w));
        }
    }
    if (t < 384) {   // W slice: (row = t>>1, ch-half = t&1)
        const int r = t >> 1, which = t & 1;
        const int grow = (r >> 6) * CH + h * HD + (r & 63);
        const float4* wg = reinterpret_cast<const float4*>(W + (size_t)grow * CH + which * 64);
        char* p = smem + WT_OFF + which * 24576;
        #pragma unroll
        for (int i = 0; i < 16; i++) {
            float4 v = wg[i];
            *reinterpret_cast<uint2*>(p + SWZ(r * 128 + i * 8)) =
                make_uint2(h2u(v.x, v.y), h2u(v.z, v.w));
        }
    }
    if (t < 192) sB[t] = bias[(t >> 6) * CH + h * HD + (t & 63)];
    __syncthreads();

    // ================= phase 1: QKV GEMM (warp = 16 token rows), fully unrolled =====
    uint32_t xa[8][4];
    #pragma unroll
    for (int kc = 0; kc < 2; kc++)
        #pragma unroll
        for (int ks = 0; ks < 4; ks++) {
            const int r = 16 * w + (lane & 15);
            const int c = ks * 16 + ((lane & 16) ? 8 : 0);
            ldsm4(xa[kc * 4 + ks], sb + XT_OFF + kc * 32768 + SWZ(r * 128 + c * 2));
        }

    uint32_t qa[4][4];                       // Q as S-GEMM A-fragments (kept in regs)
    const int row0 = 16 * w + (lane >> 2);

    #pragma unroll
    for (int nt = 0; nt < 3; nt++) {         // 0=Q 1=K 2=V  (UNROLLED)
        float fa[8][4];
        #pragma unroll
        for (int j = 0; j < 8; j++) { fa[j][0]=0.f; fa[j][1]=0.f; fa[j][2]=0.f; fa[j][3]=0.f; }

        #pragma unroll
        for (int kc = 0; kc < 2; kc++)
            #pragma unroll
            for (int ks = 0; ks < 4; ks++)
                #pragma unroll
                for (int j = 0; j < 4; j++) {
                    const int n = nt * 64 + 16 * j + (lane & 7) + ((lane & 16) ? 8 : 0);
                    const int c = ks * 16 + ((lane & 8) ? 8 : 0);
                    uint32_t b[4];
                    ldsm4(b, sb + WT_OFF + kc * 24576 + SWZ(n * 128 + c * 2));
                    mma16816(fa[2*j],   xa[kc*4+ks], b[0], b[1]);
                    mma16816(fa[2*j+1], xa[kc*4+ks], b[2], b[3]);
                }

        if (nt == 0) {
            // Q: (+bias) * (scale*log2e), convert accumulators directly to A-fragments
            #pragma unroll
            for (int ks = 0; ks < 4; ks++) {
                const float ba0 = sB[16*ks + q2],     ba1 = sB[16*ks + q2 + 1];
                const float bb0 = sB[16*ks + q2 + 8], bb1 = sB[16*ks + q2 + 9];
                qa[ks][0] = h2u((fa[2*ks][0]  + ba0) * ESC2, (fa[2*ks][1]  + ba1) * ESC2);
                qa[ks][1] = h2u((fa[2*ks][2]  + ba0) * ESC2, (fa[2*ks][3]  + ba1) * ESC2);
                qa[ks][2] = h2u((fa[2*ks+1][0]+ bb0) * ESC2, (fa[2*ks+1][1]+ bb1) * ESC2);
                qa[ks][3] = h2u((fa[2*ks+1][2]+ bb0) * ESC2, (fa[2*ks+1][3]+ bb1) * ESC2);
            }
        } else {
            char* dst = smem + (nt == 1 ? K_OFF : V_OFF);
            const int boff = nt * 64;
            #pragma unroll
            for (int j = 0; j < 8; j++) {
                const int c = 8 * j + q2;
                const float b0 = sB[boff + c], b1 = sB[boff + c + 1];
                *reinterpret_cast<uint32_t*>(dst + SWZ( row0      * 128 + c * 2)) =
                    h2u(fa[j][0] + b0, fa[j][1] + b1);
                *reinterpret_cast<uint32_t*>(dst + SWZ((row0 + 8) * 128 + c * 2)) =
                    h2u(fa[j][2] + b0, fa[j][3] + b1);
            }
        }
    }
    __syncthreads();

    // ================= phase 2: attention (warp owns 16 query rows), unrolled =======
    float oacc[8][4];
    #pragma unroll
    for (int j = 0; j < 8; j++) { oacc[j][0]=0.f; oacc[j][1]=0.f; oacc[j][2]=0.f; oacc[j][3]=0.f; }
    float rsum0 = 0.f, rsum1 = 0.f;

    #pragma unroll
    for (int kv = 0; kv < 4; kv++) {         // UNROLLED
        // S = Q K^T over 64 kv tokens (scale+log2e pre-folded into Q)
        float sacc[8][4];
        #pragma unroll
        for (int j = 0; j < 8; j++) { sacc[j][0]=0.f; sacc[j][1]=0.f; sacc[j][2]=0.f; sacc[j][3]=0.f; }

        #pragma unroll
        for (int ks = 0; ks < 4; ks++)
            #pragma unroll
            for (int j = 0; j < 4; j++) {
                const int n = kv * 64 + 16 * j + (lane & 7) + ((lane & 16) ? 8 : 0);
                const int c = ks * 16 + ((lane & 8) ? 8 : 0);
                uint32_t b[4];
                ldsm4(b, sb + K_OFF + SWZ(n * 128 + c * 2));
                mma16816(sacc[2*j],   qa[ks], b[0], b[1]);
                mma16816(sacc[2*j+1], qa[ks], b[2], b[3]);
            }

        // 2^s (bounded scores, no max-sub) -> P A-fragments
        uint32_t pf[4][4];
        #pragma unroll
        for (int ks = 0; ks < 4; ks++) {
            float e0 = ex2f(sacc[2*ks][0]),   e1 = ex2f(sacc[2*ks][1]);
            float e2 = ex2f(sacc[2*ks][2]),   e3 = ex2f(sacc[2*ks][3]);
            float f0 = ex2f(sacc[2*ks+1][0]), f1 = ex2f(sacc[2*ks+1][1]);
            float f2 = ex2f(sacc[2*ks+1][2]), f3 = ex2f(sacc[2*ks+1][3]);
            rsum0 += (e0 + e1) + (f0 + f1);
            rsum1 += (e2 + e3) + (f2 + f3);
            pf[ks][0] = h2u(e0, e1);
            pf[ks][1] = h2u(e2, e3);
            pf[ks][2] = h2u(f0, f1);
            pf[ks][3] = h2u(f2, f3);
        }

        // O += P V   (B from V[tok][ch] via ldmatrix.trans)
        #pragma unroll
        for (int ks = 0; ks < 4; ks++)
            #pragma unroll
            for (int j = 0; j < 4; j++) {
                const int tok = kv * 64 + ks * 16 + (lane & 7) + ((lane & 8) ? 8 : 0);
                const int ch  = 16 * j + ((lane & 16) ? 8 : 0);
                uint32_t b[4];
                ldsm4t(b, sb + V_OFF + SWZ(tok * 128 + ch * 2));
                mma16816(oacc[2*j],   pf[ks], b[0], b[1]);
                mma16816(oacc[2*j+1], pf[ks], b[2], b[3]);
            }
    }

    // normalize + write out
    rsum0 += __shfl_xor_sync(0xffffffffu, rsum0, 1);
    rsum0 += __shfl_xor_sync(0xffffffffu, rsum0, 2);
    rsum1 += __shfl_xor_sync(0xffffffffu, rsum1, 1);
    rsum1 += __shfl_xor_sync(0xffffffffu, rsum1, 2);
    const float inv0 = 1.0f / rsum0, inv1 = 1.0f / rsum1;

    float* o = out + ((size_t)(bl * G) + row0) * CH + h * HD;
    #pragma unroll
    for (int j = 0; j < 8; j++) {
        const int c = 8 * j + q2;
        *reinterpret_cast<float2*>(o + c) =
            make_float2(oacc[j][0] * inv0, oacc[j][1] * inv0);
        *reinterpret_cast<float2*>(o + 8 * CH + c) =
            make_float2(oacc[j][2] * inv1, oacc[j][3] * inv1);
    }
}

extern "C" void kernel_launch(void* const* d_in, const int* in_sizes, int n_in,
                              void* d_out, int out_size) {
    (void)n_in; (void)out_size;
    const float* x  = (const float*)d_in[0];
    const float* W  = (const float*)d_in[1];
    const float* b  = (const float*)d_in[2];
    float* out = (float*)d_out;

    cudaFuncSetAttribute(msa_hmma5, cudaFuncAttributeMaxDynamicSharedMemorySize, SMEM_BYTES);
    int nbl = in_sizes[0] / (G * CH);   // 512 (b,l) groups
    msa_hmma5<<<nbl * 2, NTHREADS, SMEM_BYTES>>>(x, W, b, out);
}

// round 8
// speedup vs baseline: 1.2498x; 1.0015x over previous
#include <cuda_runtime.h>
#include <cuda_fp16.h>
#include <cstdint>
#include <cstddef>

#define G   256
#define CH  128
#define HD  64
#define NTHREADS 512

// ---- smem byte offsets (tiles: [row][64 halves] = 128B rows, SW128 swizzle) ----
#define SB_OFF  0                        // bias: 192 floats
#define XT_OFF  1024                     // 2 x [256][64] fp16 (ch-chunks) = 64 KB
#define WT_OFF  (XT_OFF + 2*32768)       // 2 x [192][64] fp16 (ch-chunks) = 48 KB
#define K_OFF   (WT_OFF + 2*24576)       // [256][64] fp16                 = 32 KB
#define V_OFF   (K_OFF  + 32768)         // [256][64] fp16                 = 32 KB
#define SMEM_BYTES (V_OFF + 32768)       // 181248

#define SWZ(o) ((o) ^ (((o) >> 3) & 0x70))
#define ESC2 0.12751744f                 // (1/sqrt(128)) * log2(e)

__device__ __forceinline__ uint32_t smem_u32(const void* p) {
    uint32_t a;
    asm("{ .reg .u64 t; cvta.to.shared.u64 t, %1; cvt.u32.u64 %0, t; }" : "=r"(a) : "l"(p));
    return a;
}
__device__ __forceinline__ uint32_t h2u(float a, float b) {
    __half2 h = __floats2half2_rn(a, b);
    return *reinterpret_cast<uint32_t*>(&h);
}
__device__ __forceinline__ float ex2f(float x) {
    float r; asm("ex2.approx.f32 %0, %1;" : "=f"(r) : "f"(x)); return r;
}
__device__ __forceinline__ void ldsm4(uint32_t* r, uint32_t addr) {
    asm volatile("ldmatrix.sync.aligned.m8n8.x4.shared.b16 {%0,%1,%2,%3}, [%4];"
                 : "=r"(r[0]), "=r"(r[1]), "=r"(r[2]), "=r"(r[3]) : "r"(addr));
}
__device__ __forceinline__ void ldsm4t(uint32_t* r, uint32_t addr) {
    asm volatile("ldmatrix.sync.aligned.m8n8.x4.trans.shared.b16 {%0,%1,%2,%3}, [%4];"
                 : "=r"(r[0]), "=r"(r[1]), "=r"(r[2]), "=r"(r[3]) : "r"(addr));
}
__device__ __forceinline__ void mma16816(float* d, const uint32_t* a, uint32_t b0, uint32_t b1) {
    asm volatile("mma.sync.aligned.m16n8k16.row.col.f32.f16.f16.f32 "
        "{%0,%1,%2,%3}, {%4,%5,%6,%7}, {%8,%9}, {%0,%1,%2,%3};"
        : "+f"(d[0]), "+f"(d[1]), "+f"(d[2]), "+f"(d[3])
        : "r"(a[0]), "r"(a[1]), "r"(a[2]), "r"(a[3]), "r"(b0), "r"(b1));
}

__global__ void __launch_bounds__(NTHREADS, 1)
msa_hmma6(const float* __restrict__ x, const float* __restrict__ W,
          const float* __restrict__ bias, float* __restrict__ out)
{
    extern __shared__ char smem[];
    const uint32_t sb = smem_u32(smem);
    float* sB = reinterpret_cast<float*>(smem + SB_OFF);

    const int h  = blockIdx.x & 1;
    const int bl = blockIdx.x >> 1;
    const int t  = threadIdx.x;
    const int w  = t >> 5, lane = t & 31;
    const int q2 = 2 * (lane & 3);

    // lane-dependent fragment row/col pieces (all < 2048, i.e. inside one swizzle span)
    const int nl  = (lane & 7) + ((lane & 16) ? 8 : 0);   // B-frag row (K/W)
    const int cb8 = (lane & 8) ? 16 : 0;                   // B-frag col byte bit
    const int tl  = (lane & 7) + ((lane & 8) ? 8 : 0);     // V trans row piece
    const int vb8 = (lane & 16) ? 16 : 0;                  // V trans col byte bit

    // precomputed swizzled base addresses: inner-loop offsets are all multiples of
    // 2048 (untouched by SWZ) -> ldsm gets [Rbase + constant-immediate]
    uint32_t waddr[4], kaddr[4], vaddr[4];
    #pragma unroll
    for (int ks = 0; ks < 4; ks++) {
        waddr[ks] = sb + WT_OFF + SWZ((uint32_t)(nl * 128 + ks * 32 + cb8));
        kaddr[ks] = sb + K_OFF  + SWZ((uint32_t)(nl * 128 + ks * 32 + cb8));
    }
    #pragma unroll
    for (int j = 0; j < 4; j++)
        vaddr[j] = sb + V_OFF + SWZ((uint32_t)(tl * 128 + 32 * j + vb8));

    // ================= staging: X (all 256 tokens) + W slice + bias =================
    {   // X: thread -> (token = t>>1, ch-half = t&1): 16 float4 each
        const int tok = t >> 1, which = t & 1;
        const float4* xg = reinterpret_cast<const float4*>(
            x + ((size_t)(bl * G + tok)) * CH + which * 64);
        char* p = smem + XT_OFF + which * 32768;
        #pragma unroll
        for (int i = 0; i < 16; i++) {
            float4 v = xg[i];
            *reinterpret_cast<uint2*>(p + SWZ(tok * 128 + i * 8)) =
                make_uint2(h2u(v.x, v.y), h2u(v.z, v.w));
        }
    }
    if (t < 384) {   // W slice: (row = t>>1, ch-half = t&1)
        const int r = t >> 1, which = t & 1;
        const int grow = (r >> 6) * CH + h * HD + (r & 63);
        const float4* wg = reinterpret_cast<const float4*>(W + (size_t)grow * CH + which * 64);
        char* p = smem + WT_OFF + which * 24576;
        #pragma unroll
        for (int i = 0; i < 16; i++) {
            float4 v = wg[i];
            *reinterpret_cast<uint2*>(p + SWZ(r * 128 + i * 8)) =
                make_uint2(h2u(v.x, v.y), h2u(v.z, v.w));
        }
    }
    if (t < 192) sB[t] = bias[(t >> 6) * CH + h * HD + (t & 63)];
    __syncthreads();

    // ================= phase 1: QKV GEMM (warp = 16 token rows), fully unrolled =====
    uint32_t xa[8][4];
    #pragma unroll
    for (int kc = 0; kc < 2; kc++)
        #pragma unroll
        for (int ks = 0; ks < 4; ks++) {
            const int r = 16 * w + (lane & 15);
            const int c = ks * 16 + ((lane & 16) ? 8 : 0);
            ldsm4(xa[kc * 4 + ks], sb + XT_OFF + kc * 32768 + SWZ(r * 128 + c * 2));
        }

    uint32_t qa[4][4];                       // Q as S-GEMM A-fragments (kept in regs)
    const int row0 = 16 * w + (lane >> 2);

    #pragma unroll
    for (int nt = 0; nt < 3; nt++) {         // 0=Q 1=K 2=V  (UNROLLED)
        float fa[8][4];
        #pragma unroll
        for (int j = 0; j < 8; j++) { fa[j][0]=0.f; fa[j][1]=0.f; fa[j][2]=0.f; fa[j][3]=0.f; }

        #pragma unroll
        for (int kc = 0; kc < 2; kc++)
            #pragma unroll
            for (int ks = 0; ks < 4; ks++)
                #pragma unroll
                for (int j = 0; j < 4; j++) {
                    uint32_t b[4];
                    ldsm4(b, waddr[ks] + (uint32_t)(kc * 24576 + nt * 8192 + j * 2048));
                    mma16816(fa[2*j],   xa[kc*4+ks], b[0], b[1]);
                    mma16816(fa[2*j+1], xa[kc*4+ks], b[2], b[3]);
                }

        if (nt == 0) {
            // Q: (+bias) * (scale*log2e), convert accumulators directly to A-fragments
            #pragma unroll
            for (int ks = 0; ks < 4; ks++) {
                const float ba0 = sB[16*ks + q2],     ba1 = sB[16*ks + q2 + 1];
                const float bb0 = sB[16*ks + q2 + 8], bb1 = sB[16*ks + q2 + 9];
                qa[ks][0] = h2u((fa[2*ks][0]  + ba0) * ESC2, (fa[2*ks][1]  + ba1) * ESC2);
                qa[ks][1] = h2u((fa[2*ks][2]  + ba0) * ESC2, (fa[2*ks][3]  + ba1) * ESC2);
                qa[ks][2] = h2u((fa[2*ks+1][0]+ bb0) * ESC2, (fa[2*ks+1][1]+ bb1) * ESC2);
                qa[ks][3] = h2u((fa[2*ks+1][2]+ bb0) * ESC2, (fa[2*ks+1][3]+ bb1) * ESC2);
            }
        } else {
            char* dst = smem + (nt == 1 ? K_OFF : V_OFF);
            const int boff = nt * 64;
            #pragma unroll
            for (int j = 0; j < 8; j++) {
                const int c = 8 * j + q2;
                const float b0 = sB[boff + c], b1 = sB[boff + c + 1];
                *reinterpret_cast<uint32_t*>(dst + SWZ( row0      * 128 + c * 2)) =
                    h2u(fa[j][0] + b0, fa[j][1] + b1);
                *reinterpret_cast<uint32_t*>(dst + SWZ((row0 + 8) * 128 + c * 2)) =
                    h2u(fa[j][2] + b0, fa[j][3] + b1);
            }
        }
    }
    __syncthreads();

    // ================= phase 2: attention (warp owns 16 query rows), unrolled =======
    float oacc[8][4];
    #pragma unroll
    for (int j = 0; j < 8; j++) { oacc[j][0]=0.f; oacc[j][1]=0.f; oacc[j][2]=0.f; oacc[j][3]=0.f; }
    float rsum0 = 0.f, rsum1 = 0.f;

    #pragma unroll
    for (int kv = 0; kv < 4; kv++) {         // UNROLLED
        // S = Q K^T over 64 kv tokens (scale+log2e pre-folded into Q)
        float sacc[8][4];
        #pragma unroll
        for (int j = 0; j < 8; j++) { sacc[j][0]=0.f; sacc[j][1]=0.f; sacc[j][2]=0.f; sacc[j][3]=0.f; }

        #pragma unroll
        for (int ks = 0; ks < 4; ks++)
            #pragma unroll
            for (int j = 0; j < 4; j++) {
                uint32_t b[4];
                ldsm4(b, kaddr[ks] + (uint32_t)(kv * 8192 + j * 2048));
                mma16816(sacc[2*j],   qa[ks], b[0], b[1]);
                mma16816(sacc[2*j+1], qa[ks], b[2], b[3]);
            }

        // 2^s (bounded scores, no max-sub) -> P A-fragments
        uint32_t pf[4][4];
        #pragma unroll
        for (int ks = 0; ks < 4; ks++) {
            float e0 = ex2f(sacc[2*ks][0]),   e1 = ex2f(sacc[2*ks][1]);
            float e2 = ex2f(sacc[2*ks][2]),   e3 = ex2f(sacc[2*ks][3]);
            float f0 = ex2f(sacc[2*ks+1][0]), f1 = ex2f(sacc[2*ks+1][1]);
            float f2 = ex2f(sacc[2*ks+1][2]), f3 = ex2f(sacc[2*ks+1][3]);
            rsum0 += (e0 + e1) + (f0 + f1);
            rsum1 += (e2 + e3) + (f2 + f3);
            pf[ks][0] = h2u(e0, e1);
            pf[ks][1] = h2u(e2, e3);
            pf[ks][2] = h2u(f0, f1);
            pf[ks][3] = h2u(f2, f3);
        }

        // O += P V   (B from V[tok][ch] via ldmatrix.trans)
        #pragma unroll
        for (int ks = 0; ks < 4; ks++)
            #pragma unroll
            for (int j = 0; j < 4; j++) {
                uint32_t b[4];
                ldsm4t(b, vaddr[j] + (uint32_t)(kv * 8192 + ks * 2048));
                mma16816(oacc[2*j],   pf[ks], b[0], b[1]);
                mma16816(oacc[2*j+1], pf[ks], b[2], b[3]);
            }
    }

    // normalize + write out
    rsum0 += __shfl_xor_sync(0xffffffffu, rsum0, 1);
    rsum0 += __shfl_xor_sync(0xffffffffu, rsum0, 2);
    rsum1 += __shfl_xor_sync(0xffffffffu, rsum1, 1);
    rsum1 += __shfl_xor_sync(0xffffffffu, rsum1, 2);
    const float inv0 = 1.0f / rsum0, inv1 = 1.0f / rsum1;

    float* o = out + ((size_t)(bl * G) + row0) * CH + h * HD;
    #pragma unroll
    for (int j = 0; j < 8; j++) {
        const int c = 8 * j + q2;
        *reinterpret_cast<float2*>(o + c) =
            make_float2(oacc[j][0] * inv0, oacc[j][1] * inv0);
        *reinterpret_cast<float2*>(o + 8 * CH + c) =
            make_float2(oacc[j][2] * inv1, oacc[j][3] * inv1);
    }
}

extern "C" void kernel_launch(void* const* d_in, const int* in_sizes, int n_in,
                              void* d_out, int out_size) {
    (void)n_in; (void)out_size;
    const float* x  = (const float*)d_in[0];
    const float* W  = (const float*)d_in[1];
    const float* b  = (const float*)d_in[2];
    float* out = (float*)d_out;

    cudaFuncSetAttribute(msa_hmma6, cudaFuncAttributeMaxDynamicSharedMemorySize, SMEM_BYTES);
    int nbl = in_sizes[0] / (G * CH);   // 512 (b,l) groups
    msa_hmma6<<<nbl * 2, NTHREADS, SMEM_BYTES>>>(x, W, b, out);
}

// round 9
// speedup vs baseline: 1.7150x; 1.3722x over previous
#include <cuda_runtime.h>
#include <cuda_fp16.h>
#include <cstdint>
#include <cstddef>

#define G   256
#define CH  128
#define HD  64
#define NTHREADS 256

// ---- smem byte offsets (tiles: [row][64 halves] = 128B rows, SW128 swizzle) ----
#define SB_OFF  0                        // bias: 192 floats
#define XT_OFF  1024                     // 2 x [256][64] fp16 (ch-chunks) = 64 KB
#define WT_OFF  (XT_OFF + 2*32768)       // 2 x [192][64] fp16 (ch-chunks) = 48 KB
#define K_OFF   (WT_OFF + 2*24576)       // [256][64] fp16                 = 32 KB
#define V_OFF   (K_OFF  + 32768)         // [256][64] fp16                 = 32 KB
#define SMEM_BYTES (V_OFF + 32768)       // 181248

#define SWZ(o) ((o) ^ (((o) >> 3) & 0x70))
#define ESC2 0.12751744f                 // (1/sqrt(128)) * log2(e)

__device__ __forceinline__ uint32_t smem_u32(const void* p) {
    uint32_t a;
    asm("{ .reg .u64 t; cvta.to.shared.u64 t, %1; cvt.u32.u64 %0, t; }" : "=r"(a) : "l"(p));
    return a;
}
__device__ __forceinline__ uint32_t h2u(float a, float b) {
    __half2 h = __floats2half2_rn(a, b);
    return *reinterpret_cast<uint32_t*>(&h);
}
__device__ __forceinline__ float ex2f(float x) {
    float r; asm("ex2.approx.f32 %0, %1;" : "=f"(r) : "f"(x)); return r;
}
__device__ __forceinline__ void ldsm4(uint32_t* r, uint32_t addr) {
    asm volatile("ldmatrix.sync.aligned.m8n8.x4.shared.b16 {%0,%1,%2,%3}, [%4];"
                 : "=r"(r[0]), "=r"(r[1]), "=r"(r[2]), "=r"(r[3]) : "r"(addr));
}
__device__ __forceinline__ void ldsm4t(uint32_t* r, uint32_t addr) {
    asm volatile("ldmatrix.sync.aligned.m8n8.x4.trans.shared.b16 {%0,%1,%2,%3}, [%4];"
                 : "=r"(r[0]), "=r"(r[1]), "=r"(r[2]), "=r"(r[3]) : "r"(addr));
}
__device__ __forceinline__ void mma16816(float* d, const uint32_t* a, uint32_t b0, uint32_t b1) {
    asm volatile("mma.sync.aligned.m16n8k16.row.col.f32.f16.f16.f32 "
        "{%0,%1,%2,%3}, {%4,%5,%6,%7}, {%8,%9}, {%0,%1,%2,%3};"
        : "+f"(d[0]), "+f"(d[1]), "+f"(d[2]), "+f"(d[3])
        : "r"(a[0]), "r"(a[1]), "r"(a[2]), "r"(a[3]), "r"(b0), "r"(b1));
}

__global__ void __launch_bounds__(NTHREADS, 1)
msa_hmma7(const float* __restrict__ x, const float* __restrict__ W,
          const float* __restrict__ bias, float* __restrict__ out)
{
    extern __shared__ char smem[];
    const uint32_t sb = smem_u32(smem);
    float* sB = reinterpret_cast<float*>(smem + SB_OFF);

    const int h  = blockIdx.x & 1;
    const int bl = blockIdx.x >> 1;
    const int t  = threadIdx.x;
    const int w  = t >> 5, lane = t & 31;
    const int q2 = 2 * (lane & 3);

    // lane-dependent fragment pieces (inside one 2048B swizzle span)
    const int nl  = (lane & 7) + ((lane & 16) ? 8 : 0);   // B-frag row (K/W)
    const int cb8 = (lane & 8) ? 16 : 0;                   // B-frag col byte bit
    const int tl  = (lane & 7) + ((lane & 8) ? 8 : 0);     // V trans row piece
    const int vb8 = (lane & 16) ? 16 : 0;                  // V trans col byte bit

    uint32_t waddr[4], kaddr[4], vaddr[4];
    #pragma unroll
    for (int ks = 0; ks < 4; ks++) {
        waddr[ks] = sb + WT_OFF + SWZ((uint32_t)(nl * 128 + ks * 32 + cb8));
        kaddr[ks] = sb + K_OFF  + SWZ((uint32_t)(nl * 128 + ks * 32 + cb8));
    }
    #pragma unroll
    for (int j = 0; j < 4; j++)
        vaddr[j] = sb + V_OFF + SWZ((uint32_t)(tl * 128 + 32 * j + vb8));

    // ============ staging: coalesced LDG, conflict-free STS ============
    {   // X: 8192 float4, linear index -> lanes sweep one row's columns
        const float4* xg = reinterpret_cast<const float4*>(x + (size_t)bl * G * CH);
        #pragma unroll
        for (int k = 0; k < 32; k++) {
            const int g   = k * NTHREADS + t;
            const int row = g >> 5, c4 = g & 31;
            float4 v = xg[g];
            *reinterpret_cast<uint2*>(smem + XT_OFF + (c4 >> 4) * 32768 +
                                      SWZ(row * 128 + (c4 & 15) * 8)) =
                make_uint2(h2u(v.x, v.y), h2u(v.z, v.w));
        }
    }
    {   // W slice: 6144 float4
        #pragma unroll
        for (int k = 0; k < 24; k++) {
            const int g   = k * NTHREADS + t;
            const int row = g >> 5, c4 = g & 31;
            const int grow = (row >> 6) * CH + h * HD + (row & 63);
            float4 v = reinterpret_cast<const float4*>(W + (size_t)grow * CH)[c4];
            *reinterpret_cast<uint2*>(smem + WT_OFF + (c4 >> 4) * 24576 +
                                      SWZ(row * 128 + (c4 & 15) * 8)) =
                make_uint2(h2u(v.x, v.y), h2u(v.z, v.w));
        }
    }
    if (t < 192) sB[t] = bias[(t >> 6) * CH + h * HD + (t & 63)];
    __syncthreads();

    // ============ phase 1: QKV GEMM, warp = 32 rows x 192 cols ============
    uint32_t xa[2][8][4];                    // A frags: 2 msubs x 8 k-chunks
    #pragma unroll
    for (int m = 0; m < 2; m++)
        #pragma unroll
        for (int ks = 0; ks < 8; ks++) {
            const int r = 32 * w + 16 * m + (lane & 15);
            ldsm4(xa[m][ks], sb + XT_OFF + (ks >> 2) * 32768 +
                  SWZ((uint32_t)(r * 128 + (ks & 3) * 32 + ((lane & 16) ? 16 : 0))));
        }

    uint32_t qa[2][4][4];                    // Q as phase-2 A-fragments (in regs)
    const int row0 = 32 * w + (lane >> 2);

    #pragma unroll
    for (int chk = 0; chk < 6; chk++) {      // 6 x 32 output cols: QQ KK VV
        float fa[2][4][4];
        #pragma unroll
        for (int m = 0; m < 2; m++)
            #pragma unroll
            for (int jb = 0; jb < 4; jb++) {
                fa[m][jb][0]=0.f; fa[m][jb][1]=0.f; fa[m][jb][2]=0.f; fa[m][jb][3]=0.f;
            }

        #pragma unroll
        for (int ks = 0; ks < 8; ks++)
            #pragma unroll
            for (int j = 0; j < 2; j++) {    // 2 ldsm per k-chunk (n16 each)
                uint32_t b[4];
                ldsm4(b, waddr[ks & 3] + (uint32_t)((ks >> 2) * 24576 + chk * 4096 + j * 2048));
                mma16816(fa[0][2*j],   xa[0][ks], b[0], b[1]);
                mma16816(fa[0][2*j+1], xa[0][ks], b[2], b[3]);
                mma16816(fa[1][2*j],   xa[1][ks], b[0], b[1]);
                mma16816(fa[1][2*j+1], xa[1][ks], b[2], b[3]);
            }

        if (chk < 2) {
            // Q chunk -> A-fragments, (+bias)*(scale*log2e)
            #pragma unroll
            for (int m = 0; m < 2; m++)
                #pragma unroll
                for (int kl = 0; kl < 2; kl++) {
                    const float b0 = sB[chk*32 + 16*kl + q2],     b1 = sB[chk*32 + 16*kl + q2 + 1];
                    const float b2 = sB[chk*32 + 16*kl + q2 + 8], b3 = sB[chk*32 + 16*kl + q2 + 9];
                    qa[m][2*chk+kl][0] = h2u((fa[m][2*kl][0]  + b0) * ESC2, (fa[m][2*kl][1]  + b1) * ESC2);
                    qa[m][2*chk+kl][1] = h2u((fa[m][2*kl][2]  + b0) * ESC2, (fa[m][2*kl][3]  + b1) * ESC2);
                    qa[m][2*chk+kl][2] = h2u((fa[m][2*kl+1][0]+ b2) * ESC2, (fa[m][2*kl+1][1]+ b3) * ESC2);
                    qa[m][2*chk+kl][3] = h2u((fa[m][2*kl+1][2]+ b2) * ESC2, (fa[m][2*kl+1][3]+ b3) * ESC2);
                }
        } else {
            char* dst = smem + (chk < 4 ? K_OFF : V_OFF);
            const int col0 = (chk & 1) * 32;               // 0 or 32 within K/V tile
            #pragma unroll
            for (int m = 0; m < 2; m++) {
                const int r0 = row0 + 16 * m;
                #pragma unroll
                for (int jb = 0; jb < 4; jb++) {
                    const int cc = col0 + 8 * jb + q2;
                    const float b0 = sB[chk*32 + 8*jb + q2], b1 = sB[chk*32 + 8*jb + q2 + 1];
                    *reinterpret_cast<uint32_t*>(dst + SWZ( r0      * 128 + cc * 2)) =
                        h2u(fa[m][jb][0] + b0, fa[m][jb][1] + b1);
                    *reinterpret_cast<uint32_t*>(dst + SWZ((r0 + 8) * 128 + cc * 2)) =
                        h2u(fa[m][jb][2] + b0, fa[m][jb][3] + b1);
                }
            }
        }
    }
    __syncthreads();

    // ============ phase 2: attention, warp owns 32 query rows ============
    float oacc[2][8][4];
    #pragma unroll
    for (int m = 0; m < 2; m++)
        #pragma unroll
        for (int jb = 0; jb < 8; jb++) {
            oacc[m][jb][0]=0.f; oacc[m][jb][1]=0.f; oacc[m][jb][2]=0.f; oacc[m][jb][3]=0.f;
        }
    float rsum[2][2] = {{0.f,0.f},{0.f,0.f}};

    #pragma unroll
    for (int kv = 0; kv < 4; kv++) {
        // S = Q K^T over 64 kv tokens
        float sacc[2][8][4];
        #pragma unroll
        for (int m = 0; m < 2; m++)
            #pragma unroll
            for (int jb = 0; jb < 8; jb++) {
                sacc[m][jb][0]=0.f; sacc[m][jb][1]=0.f; sacc[m][jb][2]=0.f; sacc[m][jb][3]=0.f;
            }

        #pragma unroll
        for (int ks = 0; ks < 4; ks++)
            #pragma unroll
            for (int j = 0; j < 4; j++) {
                uint32_t b[4];
                ldsm4(b, kaddr[ks] + (uint32_t)(kv * 8192 + j * 2048));
                mma16816(sacc[0][2*j],   qa[0][ks], b[0], b[1]);
                mma16816(sacc[0][2*j+1], qa[0][ks], b[2], b[3]);
                mma16816(sacc[1][2*j],   qa[1][ks], b[0], b[1]);
                mma16816(sacc[1][2*j+1], qa[1][ks], b[2], b[3]);
            }

        // 2^s -> P A-fragments (scores bounded; no max-sub)
        uint32_t pf[2][4][4];
        #pragma unroll
        for (int m = 0; m < 2; m++)
            #pragma unroll
            for (int ks = 0; ks < 4; ks++) {
                float e0 = ex2f(sacc[m][2*ks][0]),   e1 = ex2f(sacc[m][2*ks][1]);
                float e2 = ex2f(sacc[m][2*ks][2]),   e3 = ex2f(sacc[m][2*ks][3]);
                float f0 = ex2f(sacc[m][2*ks+1][0]), f1 = ex2f(sacc[m][2*ks+1][1]);
                float f2 = ex2f(sacc[m][2*ks+1][2]), f3 = ex2f(sacc[m][2*ks+1][3]);
                rsum[m][0] += (e0 + e1) + (f0 + f1);
                rsum[m][1] += (e2 + e3) + (f2 + f3);
                pf[m][ks][0] = h2u(e0, e1);
                pf[m][ks][1] = h2u(e2, e3);
                pf[m][ks][2] = h2u(f0, f1);
                pf[m][ks][3] = h2u(f2, f3);
            }

        // O += P V
        #pragma unroll
        for (int ks = 0; ks < 4; ks++)
            #pragma unroll
            for (int j = 0; j < 4; j++) {
                uint32_t b[4];
                ldsm4t(b, vaddr[j] + (uint32_t)(kv * 8192 + ks * 2048));
                mma16816(oacc[0][2*j],   pf[0][ks], b[0], b[1]);
                mma16816(oacc[0][2*j+1], pf[0][ks], b[2], b[3]);
                mma16816(oacc[1][2*j],   pf[1][ks], b[0], b[1]);
                mma16816(oacc[1][2*j+1], pf[1][ks], b[2], b[3]);
            }
    }

    // normalize + write out (both msubs)
    #pragma unroll
    for (int m = 0; m < 2; m++) {
        float r0s = rsum[m][0], r1s = rsum[m][1];
        r0s += __shfl_xor_sync(0xffffffffu, r0s, 1);
        r0s += __shfl_xor_sync(0xffffffffu, r0s, 2);
        r1s += __shfl_xor_sync(0xffffffffu, r1s, 1);
        r1s += __shfl_xor_sync(0xffffffffu, r1s, 2);
        const float inv0 = 1.0f / r0s, inv1 = 1.0f / r1s;

        float* o = out + ((size_t)(bl * G) + row0 + 16 * m) * CH + h * HD;
        #pragma unroll
        for (int jb = 0; jb < 8; jb++) {
            const int c = 8 * jb + q2;
            *reinterpret_cast<float2*>(o + c) =
                make_float2(oacc[m][jb][0] * inv0, oacc[m][jb][1] * inv0);
            *reinterpret_cast<float2*>(o + 8 * CH + c) =
                make_float2(oacc[m][jb][2] * inv1, oacc[m][jb][3] * inv1);
        }
    }
}

extern "C" void kernel_launch(void* const* d_in, const int* in_sizes, int n_in,
                              void* d_out, int out_size) {
    (void)n_in; (void)out_size;
    const float* x  = (const float*)d_in[0];
    const float* W  = (const float*)d_in[1];
    const float* b  = (const float*)d_in[2];
    float* out = (float*)d_out;

    cudaFuncSetAttribute(msa_hmma7, cudaFuncAttributeMaxDynamicSharedMemorySize, SMEM_BYTES);
    int nbl = in_sizes[0] / (G * CH);   // 512 (b,l) groups
    msa_hmma7<<<nbl * 2, NTHREADS, SMEM_BYTES>>>(x, W, b, out);
}